// round 15
// baseline (speedup 1.0000x reference)
#include <cuda_runtime.h>
#include <math.h>
#include <stdint.h>

#define DIN 4096
#define NH  4096
#define GRIDN 148            // persistent: one CTA per SM
#define NTHREADS 256
#define NWARPS (NTHREADS/32)
#define CHUNK 2048           // columns per pipeline stage
#define ROWB  (CHUNK * 4)    // 8192 B per row-chunk
#define STAGEB (7 * ROWB)    // 57344 B per stage (7 weight rows)
#define SMEM_BYTES (2 * STAGEB)  // double buffer: 114688 B dynamic

// Per element j (7 weight rows; o-gate x-part aliases the g row per the
// reference quirk Wio == Wih[2nh:3nh]; Wih[3nh:4nh] never read -> 448 MB floor):
//   slots 0..2: Wih rows j, nh+j, 2nh+j        (dot with x)
//   slots 3..6: Whh rows j, nh+j, 2nh+j, 3nh+j (dot with h)
// cp.async.bulk streams each row-chunk as one contiguous 8 KB burst through
// the TMA engine (bypasses LSU/L1tex); compute reads SMEM.

__device__ __forceinline__ uint32_t s2u(const void* p) {
    return (uint32_t)__cvta_generic_to_shared(p);
}

__device__ __forceinline__ float warp_sum(float v) {
    #pragma unroll
    for (int off = 16; off > 0; off >>= 1)
        v += __shfl_xor_sync(0xFFFFFFFFu, v, off);
    return v;
}

__device__ __forceinline__ float sigmoidf_(float v) {
    return 1.0f / (1.0f + __expf(-v));
}

__device__ __forceinline__ float dot4(const float4 a, const float4 b) {
    return a.x * b.x + a.y * b.y + a.z * b.z + a.w * b.w;
}

__device__ __forceinline__ void mbar_wait(uint32_t mbar, uint32_t parity) {
    asm volatile(
        "{\n\t.reg .pred P1;\n\t"
        "WAIT_%=:\n\t"
        "mbarrier.try_wait.parity.acquire.cta.shared::cta.b64 P1, [%0], %1, 0x989680;\n\t"
        "@P1 bra.uni DONE_%=;\n\t"
        "bra.uni WAIT_%=;\n\t"
        "DONE_%=:\n\t}"
        :: "r"(mbar), "r"(parity) : "memory");
}

__device__ __forceinline__ void issue_stage(
    uint32_t dstbuf, uint32_t mbar,
    const float* __restrict__ Wih, const float* __restrict__ Whh,
    int e, int c)
{
    asm volatile("mbarrier.arrive.expect_tx.shared.b64 _, [%0], %1;"
                 :: "r"(mbar), "r"((uint32_t)STAGEB) : "memory");
    const size_t off = (size_t)c * CHUNK;
    const float* srcs[7] = {
        Wih + (size_t)e * DIN            + off,
        Wih + (size_t)(NH + e) * DIN     + off,
        Wih + (size_t)(2 * NH + e) * DIN + off,
        Whh + (size_t)e * NH             + off,
        Whh + (size_t)(NH + e) * NH      + off,
        Whh + (size_t)(2 * NH + e) * NH  + off,
        Whh + (size_t)(3 * NH + e) * NH  + off };
    #pragma unroll
    for (int r = 0; r < 7; r++) {
        asm volatile(
            "cp.async.bulk.shared::cluster.global.mbarrier::complete_tx::bytes "
            "[%0], [%1], %2, [%3];"
            :: "r"(dstbuf + r * ROWB), "l"(srcs[r]), "r"((uint32_t)ROWB), "r"(mbar)
            : "memory");
    }
}

__global__ __launch_bounds__(NTHREADS) void lstm_tma_kernel(
    const float* __restrict__ x,
    const float* __restrict__ h,
    const float* __restrict__ c_in,
    const float* __restrict__ Wih,
    const float* __restrict__ Whh,
    const float* __restrict__ bih,
    const float* __restrict__ bhh,
    float* __restrict__ out)
{
    extern __shared__ float smem_dyn[];
    __shared__ uint64_t mbar_s[2];
    __shared__ float partials[NWARPS][7];

    const int tid  = threadIdx.x;
    const int w    = tid >> 5;
    const int lane = tid & 31;
    const int bid  = blockIdx.x;

    const uint32_t buf0 = s2u(smem_dyn);
    const uint32_t bufs[2] = { buf0, buf0 + (uint32_t)STAGEB };
    const uint32_t mb[2]   = { s2u(&mbar_s[0]), s2u(&mbar_s[1]) };

    if (tid == 0) {
        asm volatile("mbarrier.init.shared.b64 [%0], %1;" :: "r"(mb[0]), "r"(1u));
        asm volatile("mbarrier.init.shared.b64 [%0], %1;" :: "r"(mb[1]), "r"(1u));
        asm volatile("fence.proxy.async.shared::cta;" ::: "memory");
    }
    __syncthreads();

    const int nE = (NH - bid + GRIDN - 1) / GRIDN;   // 27 or 28 elements

    // Prologue: fill both buffers with element 0's two chunks.
    if (tid == 0) {
        issue_stage(bufs[0], mb[0], Wih, Whh, bid, 0);
        issue_stage(bufs[1], mb[1], Wih, Whh, bid, 1);
    }

    const float4* __restrict__ x4 = (const float4*)x;
    const float4* __restrict__ h4 = (const float4*)h;

    for (int k = 0; k < nE; k++) {
        const int e = bid + k * GRIDN;
        const uint32_t parity = (uint32_t)(k & 1);
        float acc[7] = {0.f, 0.f, 0.f, 0.f, 0.f, 0.f, 0.f};

        #pragma unroll
        for (int c = 0; c < 2; c++) {
            mbar_wait(mb[c], parity);

            const float4* buf4 = (const float4*)(smem_dyn + (size_t)c * (STAGEB / 4));
            const int base = w * 64 + lane;   // float4 idx within chunk [0,512)

            #pragma unroll
            for (int ii = 0; ii < 2; ii++) {
                const int i = base + ii * 32;
                const float4 xq = __ldg(&x4[c * 512 + i]);
                const float4 hq = __ldg(&h4[c * 512 + i]);
                const float4 w0 = buf4[0 * 512 + i];
                const float4 w1 = buf4[1 * 512 + i];
                const float4 w2 = buf4[2 * 512 + i];
                const float4 w3 = buf4[3 * 512 + i];
                const float4 w4 = buf4[4 * 512 + i];
                const float4 w5 = buf4[5 * 512 + i];
                const float4 w6 = buf4[6 * 512 + i];
                acc[0] += dot4(w0, xq);
                acc[1] += dot4(w1, xq);
                acc[2] += dot4(w2, xq);
                acc[3] += dot4(w3, hq);
                acc[4] += dot4(w4, hq);
                acc[5] += dot4(w5, hq);
                acc[6] += dot4(w6, hq);
            }

            if (c == 1) {
                #pragma unroll
                for (int r = 0; r < 7; r++) acc[r] = warp_sum(acc[r]);
                if (lane == 0) {
                    #pragma unroll
                    for (int r = 0; r < 7; r++) partials[w][r] = acc[r];
                }
            }

            // All warps done reading buffer c (and partials written for c==1).
            __syncthreads();

            if (tid == 0) {
                // Refill this buffer with the NEXT element's same chunk first
                // (keep the TMA queue fed), then do the epilogue.
                if (k + 1 < nE)
                    issue_stage(bufs[c], mb[c], Wih, Whh, e + GRIDN, c);

                if (c == 1) {
                    float A0 = 0.f, A1 = 0.f, A2 = 0.f, A3 = 0.f,
                          A4 = 0.f, A5 = 0.f, A6 = 0.f;
                    #pragma unroll
                    for (int wi = 0; wi < NWARPS; wi++) {
                        A0 += partials[wi][0];
                        A1 += partials[wi][1];
                        A2 += partials[wi][2];
                        A3 += partials[wi][3];
                        A4 += partials[wi][4];
                        A5 += partials[wi][5];
                        A6 += partials[wi][6];
                    }
                    const float zi = A0 + A3 + __ldg(bih + e)          + __ldg(bhh + e);
                    const float zf = A1 + A4 + __ldg(bih + NH + e)     + __ldg(bhh + NH + e);
                    const float zg = A2 + A5 + __ldg(bih + 2 * NH + e) + __ldg(bhh + 2 * NH + e);
                    const float zo = A2 + A6 + __ldg(bih + 3 * NH + e) + __ldg(bhh + 3 * NH + e);

                    const float it = sigmoidf_(zi);
                    const float ft = sigmoidf_(zf);
                    const float gt = tanhf(zg);
                    const float ot = sigmoidf_(zo);
                    const float ct = ft * __ldg(c_in + e) + it * gt;
                    const float ht = ot * tanhf(ct);

                    out[e]          = it;
                    out[NH + e]     = ft;
                    out[2 * NH + e] = gt;
                    out[3 * NH + e] = ot;
                    out[4 * NH + e] = ct;
                    out[5 * NH + e] = ht;
                }
            }
        }
    }
}

extern "C" void kernel_launch(void* const* d_in, const int* in_sizes, int n_in,
                              void* d_out, int out_size)
{
    // metadata order: x, h, c, Wih, Whh, bih, bhh
    const float* x   = (const float*)d_in[0];
    const float* h   = (const float*)d_in[1];
    const float* c   = (const float*)d_in[2];
    const float* Wih = (const float*)d_in[3];
    const float* Whh = (const float*)d_in[4];
    const float* bih = (const float*)d_in[5];
    const float* bhh = (const float*)d_in[6];
    float* out = (float*)d_out;

    cudaFuncSetAttribute(lstm_tma_kernel,
                         cudaFuncAttributeMaxDynamicSharedMemorySize, SMEM_BYTES);

    lstm_tma_kernel<<<GRIDN, NTHREADS, SMEM_BYTES>>>(
        x, h, c, Wih, Whh, bih, bhh, out);
}